// round 10
// baseline (speedup 1.0000x reference)
#include <cuda_runtime.h>
#include <cuda_fp16.h>
#include <math.h>

#define BS   2
#define SEQ  2048
#define DMODEL 1024
#define NH   16
#define HD   64
#define M_GEMM 4096
#define N_GEMM 3072
#define K_GEMM 1024
#define ELEMS (BS*SEQ*DMODEL)

// fp16 planes (packed pairs as unsigned). Device globals => no allocation.
__device__ unsigned g_Xh[M_GEMM*K_GEMM/2];                    // X hi only
__device__ unsigned g_Wh[N_GEMM*K_GEMM/2], g_Wl[N_GEMM*K_GEMM/2];  // W*64 hi/lo
__device__ unsigned g_Qh[ELEMS/2];                            // Q * 0.125*log2e, hi only
__device__ unsigned g_Kh[ELEMS/2], g_Kl[ELEMS/2];
__device__ unsigned g_Vh[ELEMS/2], g_Vl[ELEMS/2];

extern __shared__ __align__(16) char dynsmem[];

#define QSCALE (0.125f * 1.44269504088896f)   // fold 1/sqrt(64) and log2(e) into Q

// ---------------------------------------------------------------------------
// helpers
// ---------------------------------------------------------------------------
__device__ __forceinline__ unsigned pack_h(float a, float b) {
    __half2 t = __floats2half2_rn(a, b);
    return *reinterpret_cast<unsigned*>(&t);
}
__device__ __forceinline__ void split_pack_h(float a, float b, unsigned& h, unsigned& l) {
    __half ah = __float2half_rn(a);
    __half bh = __float2half_rn(b);
    __half2 hv; hv.x = ah; hv.y = bh;
    h = *reinterpret_cast<unsigned*>(&hv);
    l = pack_h(a - __half2float(ah), b - __half2float(bh));
}
__device__ __forceinline__ void mma16816(float* d, const unsigned* a, unsigned b0, unsigned b1) {
    asm volatile(
        "mma.sync.aligned.m16n8k16.row.col.f32.f16.f16.f32 "
        "{%0,%1,%2,%3}, {%4,%5,%6,%7}, {%8,%9}, {%0,%1,%2,%3};"
        : "+f"(d[0]), "+f"(d[1]), "+f"(d[2]), "+f"(d[3])
        : "r"(a[0]), "r"(a[1]), "r"(a[2]), "r"(a[3]), "r"(b0), "r"(b1));
}
__device__ __forceinline__ unsigned smem_u32(const void* p) {
    return (unsigned)__cvta_generic_to_shared(p);
}
__device__ __forceinline__ void ldsm_x4(unsigned& r0, unsigned& r1, unsigned& r2, unsigned& r3, unsigned addr) {
    asm volatile("ldmatrix.sync.aligned.m8n8.x4.shared.b16 {%0,%1,%2,%3}, [%4];"
                 : "=r"(r0), "=r"(r1), "=r"(r2), "=r"(r3) : "r"(addr));
}
__device__ __forceinline__ void ldsm_x4_t(unsigned& r0, unsigned& r1, unsigned& r2, unsigned& r3, unsigned addr) {
    asm volatile("ldmatrix.sync.aligned.m8n8.x4.trans.shared.b16 {%0,%1,%2,%3}, [%4];"
                 : "=r"(r0), "=r"(r1), "=r"(r2), "=r"(r3) : "r"(addr));
}
__device__ __forceinline__ void cp16(unsigned dst, const void* src) {
    asm volatile("cp.async.cg.shared.global [%0], [%1], 16;" :: "r"(dst), "l"(src));
}
__device__ __forceinline__ void cp_commit() { asm volatile("cp.async.commit_group;" ::: "memory"); }
__device__ __forceinline__ void cp_wait0() { asm volatile("cp.async.wait_group 0;" ::: "memory"); }
__device__ __forceinline__ void cp_wait1() { asm volatile("cp.async.wait_group 1;" ::: "memory"); }
__device__ __forceinline__ float ex2f(float x) {
    float r; asm("ex2.approx.f32 %0, %1;" : "=f"(r) : "f"(x)); return r;
}

// ---------------------------------------------------------------------------
// Kernel 0: X -> fp16 hi plane; W*64 -> fp16 hi/lo planes
// ---------------------------------------------------------------------------
__global__ void convert_planes(const float4* __restrict__ X4, const float4* __restrict__ W4)
{
    const int i0 = blockIdx.x * blockDim.x + threadIdx.x;
    const int stride = gridDim.x * blockDim.x;
    for (int idx = i0; idx < M_GEMM * K_GEMM / 4; idx += stride) {
        float4 v = X4[idx];
        g_Xh[2*idx]   = pack_h(v.x, v.y);
        g_Xh[2*idx+1] = pack_h(v.z, v.w);
    }
    for (int idx = i0; idx < N_GEMM * K_GEMM / 4; idx += stride) {
        float4 v = W4[idx];
        unsigned h0, l0, h1, l1;
        split_pack_h(v.x * 64.f, v.y * 64.f, h0, l0);
        split_pack_h(v.z * 64.f, v.w * 64.f, h1, l1);
        g_Wh[2*idx] = h0; g_Wh[2*idx+1] = h1;
        g_Wl[2*idx] = l0; g_Wl[2*idx+1] = l1;
    }
}

// ---------------------------------------------------------------------------
// Kernel 1: QKV GEMM, fp16 2-term (Xh*Wh + Xh*Wl), 2-stage cp.async pipeline.
// 128x128 tile, BK=32, 256 threads = 8 warps (2m x 4n).
// ---------------------------------------------------------------------------
#define GST 40                         // smem row stride (80B)
#define PS_G (128*GST*2)               // plane bytes 10240
#define STG_G (3*PS_G)                 // stage bytes 30720 (Ah, Bh, Bl)

__global__ __launch_bounds__(256, 2)
void qkv_gemm_tc(const float* __restrict__ bias,
                 float* __restrict__ Kout, float* __restrict__ Vout)
{
    const int tid = threadIdx.x;
    const int w = tid >> 5, lane = tid & 31;
    const int wm = w & 1, wn = w >> 1;
    const int gr = lane >> 2, qc = lane & 3;
    const int bm = blockIdx.y * 128, bn = blockIdx.x * 128;

    const unsigned sbase = smem_u32(dynsmem);
    const int lrow = tid >> 1;
    const int ch0  = (tid & 1) * 2;

    const size_t arow0 = (size_t)(bm + lrow) * (K_GEMM/2);
    const size_t brow0 = (size_t)(bn + lrow) * (K_GEMM/2);
    const unsigned doff_base = lrow * (GST*2);

    auto issue_load = [&](int kb, int s) {
        const unsigned st = sbase + s * STG_G;
        const size_t ar = arow0 + kb * 16;
        const size_t br = brow0 + kb * 16;
        #pragma unroll
        for (int c = 0; c < 2; c++) {
            const int ch = ch0 + c;
            const unsigned doff = doff_base + ch * 16;
            cp16(st          + doff, &g_Xh[ar + ch*4]);
            cp16(st + PS_G   + doff, &g_Wh[br + ch*4]);
            cp16(st + 2*PS_G + doff, &g_Wl[br + ch*4]);
        }
    };

    float acc[4][4][4];
    #pragma unroll
    for (int i = 0; i < 4; i++)
        #pragma unroll
        for (int j = 0; j < 4; j++)
            #pragma unroll
            for (int e = 0; e < 4; e++) acc[i][j][e] = 0.f;

    issue_load(0, 0); cp_commit();

    const unsigned acol_b = (lane >> 4) * 16;
    const unsigned arow_f = (lane & 15);
    const unsigned bcol_b = ((lane >> 3) & 1) * 16;
    const unsigned brow_f = ((lane >> 4) << 3) + (lane & 7);

    #pragma unroll 1
    for (int kb = 0; kb < 32; kb++) {
        const int cur = kb & 1;
        if (kb < 31) { issue_load(kb + 1, cur ^ 1); cp_commit(); cp_wait1(); }
        else cp_wait0();
        __syncthreads();

        const unsigned sAh = sbase + cur * STG_G;
        const unsigned sBh = sAh + PS_G;
        const unsigned sBl = sAh + 2*PS_G;

        #pragma unroll
        for (int kt = 0; kt < 2; kt++) {
            unsigned ah[4][4];
            const unsigned acol = kt*32 + acol_b;
            #pragma unroll
            for (int i = 0; i < 4; i++) {
                const unsigned aoff = (unsigned)(wm*64 + i*16 + arow_f) * (GST*2) + acol;
                ldsm_x4(ah[i][0], ah[i][1], ah[i][2], ah[i][3], sAh + aoff);
            }
            const unsigned bcol = kt*32 + bcol_b;
            #pragma unroll
            for (int jp = 0; jp < 2; jp++) {
                const unsigned boff = (unsigned)(wn*32 + jp*16 + brow_f) * (GST*2) + bcol;
                unsigned h0,h1,h2,h3, l0,l1,l2,l3;
                ldsm_x4(h0, h1, h2, h3, sBh + boff);
                ldsm_x4(l0, l1, l2, l3, sBl + boff);
                #pragma unroll
                for (int i = 0; i < 4; i++) {
                    mma16816(acc[i][2*jp],   ah[i], h0, h1);
                    mma16816(acc[i][2*jp],   ah[i], l0, l1);
                    mma16816(acc[i][2*jp+1], ah[i], h2, h3);
                    mma16816(acc[i][2*jp+1], ah[i], l2, l3);
                }
            }
        }
        __syncthreads();
    }

    // ---- epilogue: acc/64 + bias; scatter fp32 K/V + fp16 planes ----
    #pragma unroll
    for (int i = 0; i < 4; i++) {
        #pragma unroll
        for (int eh = 0; eh < 2; eh++) {
            const int m = bm + wm*64 + i*16 + gr + eh*8;
            const int bb = m >> 11;
            const int s  = m & (SEQ - 1);
            #pragma unroll
            for (int j = 0; j < 4; j++) {
                const int n = bn + wn*32 + j*8 + qc*2;     // even
                const int t = n >> 10;
                const int hh = (n >> 6) & (NH - 1);
                const int d = n & (HD - 1);
                const float2 bv = *(const float2*)&bias[n];
                const float v0 = acc[i][j][2*eh]   * 0.015625f + bv.x;
                const float v1 = acc[i][j][2*eh+1] * 0.015625f + bv.y;
                const size_t idx = (((size_t)(bb*NH + hh))*SEQ + s)*HD + d;
                if (t == 0) {
                    g_Qh[idx>>1] = pack_h(v0 * QSCALE, v1 * QSCALE);
                } else if (t == 1) {
                    unsigned hp, lp; split_pack_h(v0, v1, hp, lp);
                    *(float2*)&Kout[idx] = make_float2(v0, v1);
                    g_Kh[idx>>1] = hp; g_Kl[idx>>1] = lp;
                } else {
                    unsigned hp, lp; split_pack_h(v0, v1, hp, lp);
                    *(float2*)&Vout[idx] = make_float2(v0, v1);
                    g_Vh[idx>>1] = hp; g_Vl[idx>>1] = lp;
                }
            }
        }
    }
}

// ---------------------------------------------------------------------------
// Kernel 2: causal flash attention, fp16. S = Qh*(Kh+Kl) (2 MMAs/step),
// PV 3-term. Single-buffered smem, 4 blocks/SM, exp2-domain softmax.
// ---------------------------------------------------------------------------
#define KST 72
#define PS_A (64*KST*2)                // 9216
#define STG_A (4*PS_A)                 // 36864

__global__ __launch_bounds__(128, 4)
void attn_tc(float* __restrict__ Out)
{
    const int bh = blockIdx.y;
    const int b = bh >> 4, h = bh & (NH - 1);
    const int qt = gridDim.x - 1 - blockIdx.x;     // heavy blocks first
    const int tid = threadIdx.x, w = tid >> 5, lane = tid & 31;
    const int gr = lane >> 2, qc = lane & 3;
    const int m0 = qt * 64 + w * 16;

    const unsigned sbase = smem_u32(dynsmem);
    const size_t qbase = (size_t)bh * SEQ;

    // Q hi fragments only (pre-scaled by 0.125*log2e)
    unsigned qh[4][4];
    #pragma unroll
    for (int kk = 0; kk < 4; kk++) {
        #pragma unroll
        for (int e = 0; e < 4; e++) {
            const int r = m0 + gr + (e & 1) * 8;
            const int c = kk*16 + qc*2 + (e >> 1) * 8;
            qh[kk][e] = g_Qh[(qbase + r) * 32 + (c >> 1)];
        }
    }

    float Oa[8][4];
    #pragma unroll
    for (int jd = 0; jd < 8; jd++)
        #pragma unroll
        for (int e = 0; e < 4; e++) Oa[jd][e] = 0.f;
    float mrow0 = -INFINITY, mrow1 = -INFINITY, lsum0 = 0.f, lsum1 = 0.f;

    const int lrow = tid >> 1;
    const int ch0  = (tid & 1) * 4;
    const unsigned doff_base = lrow * (KST*2);

    const unsigned sKh = sbase;
    const unsigned sKl = sbase + PS_A;
    const unsigned sVh = sbase + 2*PS_A;
    const unsigned sVl = sbase + 3*PS_A;

    const unsigned krow_f = ((lane >> 4) << 3) + (lane & 7);
    const unsigned kcol_b = ((lane >> 3) & 1) * 16;
    const unsigned vrow_f = (lane & 15);
    const unsigned vcol_b = (lane >> 4) * 16;

    #pragma unroll 1
    for (int kt = 0; kt <= qt; kt++) {
        // ---- single-buffer load (cross-block overlap hides latency) ----
        const size_t rowb = (qbase + kt*64 + lrow) * 32;
        #pragma unroll
        for (int c = 0; c < 4; c++) {
            const int ch = ch0 + c;
            const unsigned doff = doff_base + ch * 16;
            cp16(sKh + doff, &g_Kh[rowb + ch*4]);
            cp16(sKl + doff, &g_Kl[rowb + ch*4]);
            cp16(sVh + doff, &g_Vh[rowb + ch*4]);
            cp16(sVl + doff, &g_Vl[rowb + ch*4]);
        }
        cp_commit(); cp_wait0();
        __syncthreads();

        // ---- S = Qh (Kh + Kl): 2 MMAs per fragment pair ----
        float S[8][4];
        #pragma unroll
        for (int j = 0; j < 8; j++)
            #pragma unroll
            for (int e = 0; e < 4; e++) S[j][e] = 0.f;

        #pragma unroll
        for (int kk = 0; kk < 4; kk++) {
            const unsigned kcol = kk*32 + kcol_b;
            #pragma unroll
            for (int jp = 0; jp < 4; jp++) {
                const unsigned koff = (jp*16 + krow_f) * (KST*2) + kcol;
                unsigned h0,h1,h2,h3, l0,l1,l2,l3;
                ldsm_x4(h0, h1, h2, h3, sKh + koff);
                ldsm_x4(l0, l1, l2, l3, sKl + koff);
                mma16816(S[2*jp],   qh[kk], h0, h1);
                mma16816(S[2*jp],   qh[kk], l0, l1);
                mma16816(S[2*jp+1], qh[kk], h2, h3);
                mma16816(S[2*jp+1], qh[kk], l2, l3);
            }
        }

        // ---- causal mask on diagonal tile ----
        if (kt == qt) {
            const int r0 = w*16 + gr, r1 = r0 + 8;
            #pragma unroll
            for (int j = 0; j < 8; j++) {
                const int cn = j*8 + qc*2;
                if (cn     > r0) S[j][0] = -1e30f;
                if (cn + 1 > r0) S[j][1] = -1e30f;
                if (cn     > r1) S[j][2] = -1e30f;
                if (cn + 1 > r1) S[j][3] = -1e30f;
            }
        }

        // ---- online softmax (base-2 domain) ----
        float mx0 = -1e30f, mx1 = -1e30f;
        #pragma unroll
        for (int j = 0; j < 8; j++) {
            mx0 = fmaxf(mx0, fmaxf(S[j][0], S[j][1]));
            mx1 = fmaxf(mx1, fmaxf(S[j][2], S[j][3]));
        }
        mx0 = fmaxf(mx0, __shfl_xor_sync(0xffffffff, mx0, 1));
        mx0 = fmaxf(mx0, __shfl_xor_sync(0xffffffff, mx0, 2));
        mx1 = fmaxf(mx1, __shfl_xor_sync(0xffffffff, mx1, 1));
        mx1 = fmaxf(mx1, __shfl_xor_sync(0xffffffff, mx1, 2));

        const float mnew0 = fmaxf(mrow0, mx0), mnew1 = fmaxf(mrow1, mx1);
        const float alpha0 = ex2f(mrow0 - mnew0), alpha1 = ex2f(mrow1 - mnew1);
        mrow0 = mnew0; mrow1 = mnew1;
        lsum0 *= alpha0; lsum1 *= alpha1;
        #pragma unroll
        for (int jd = 0; jd < 8; jd++) {
            Oa[jd][0] *= alpha0; Oa[jd][1] *= alpha0;
            Oa[jd][2] *= alpha1; Oa[jd][3] *= alpha1;
        }

        float rs0 = 0.f, rs1 = 0.f;
        #pragma unroll
        for (int j = 0; j < 8; j++) {
            S[j][0] = ex2f(S[j][0] - mnew0);
            S[j][1] = ex2f(S[j][1] - mnew0);
            S[j][2] = ex2f(S[j][2] - mnew1);
            S[j][3] = ex2f(S[j][3] - mnew1);
            rs0 += S[j][0] + S[j][1];
            rs1 += S[j][2] + S[j][3];
        }
        rs0 += __shfl_xor_sync(0xffffffff, rs0, 1);
        rs0 += __shfl_xor_sync(0xffffffff, rs0, 2);
        rs1 += __shfl_xor_sync(0xffffffff, rs1, 1);
        rs1 += __shfl_xor_sync(0xffffffff, rs1, 2);
        lsum0 += rs0; lsum1 += rs1;

        // ---- O += P V (3-term fp16) ----
        #pragma unroll
        for (int kk = 0; kk < 4; kk++) {
            unsigned pp[4], pl[4];
            const int j0 = kk*2, j1 = kk*2 + 1;
            split_pack_h(S[j0][0], S[j0][1], pp[0], pl[0]);
            split_pack_h(S[j0][2], S[j0][3], pp[1], pl[1]);
            split_pack_h(S[j1][0], S[j1][1], pp[2], pl[2]);
            split_pack_h(S[j1][2], S[j1][3], pp[3], pl[3]);
            const unsigned vrow = (kk*16 + vrow_f) * (KST*2);
            #pragma unroll
            for (int jp = 0; jp < 4; jp++) {
                const unsigned voff = vrow + jp*32 + vcol_b;
                unsigned vh0,vh1,vh2,vh3, vl0,vl1,vl2,vl3;
                ldsm_x4_t(vh0, vh1, vh2, vh3, sVh + voff);
                ldsm_x4_t(vl0, vl1, vl2, vl3, sVl + voff);
                mma16816(Oa[2*jp],   pp, vh0, vh1);
                mma16816(Oa[2*jp],   pp, vl0, vl1);
                mma16816(Oa[2*jp],   pl, vh0, vh1);
                mma16816(Oa[2*jp+1], pp, vh2, vh3);
                mma16816(Oa[2*jp+1], pp, vl2, vl3);
                mma16816(Oa[2*jp+1], pl, vh2, vh3);
            }
        }
        __syncthreads();
    }

    const float inv0 = 1.f / lsum0, inv1 = 1.f / lsum1;
    float* Op = Out + ((size_t)b * SEQ + m0) * DMODEL + h * HD;
    #pragma unroll
    for (int jd = 0; jd < 8; jd++) {
        const int c = jd*8 + qc*2;
        float2 v0; v0.x = Oa[jd][0] * inv0; v0.y = Oa[jd][1] * inv0;
        float2 v1; v1.x = Oa[jd][2] * inv1; v1.y = Oa[jd][3] * inv1;
        *(float2*)&Op[(size_t)gr * DMODEL + c]       = v0;
        *(float2*)&Op[(size_t)(gr + 8) * DMODEL + c] = v1;
    }
}

// ---------------------------------------------------------------------------
extern "C" void kernel_launch(void* const* d_in, const int* in_sizes, int n_in,
                              void* d_out, int out_size)
{
    const float* X    = (const float*)d_in[0];
    const float* Wqkv = (const float*)d_in[1];
    const float* bqkv = (const float*)d_in[2];

    float* out  = (float*)d_out;
    float* Kout = (float*)d_out + ELEMS;
    float* Vout = (float*)d_out + 2 * (size_t)ELEMS;

    static bool attr_done = false;
    if (!attr_done) {
        cudaFuncSetAttribute(qkv_gemm_tc, cudaFuncAttributeMaxDynamicSharedMemorySize, 2 * STG_G);
        cudaFuncSetAttribute(attn_tc,     cudaFuncAttributeMaxDynamicSharedMemorySize, STG_A);
        attr_done = true;
    }

    convert_planes<<<512, 256>>>((const float4*)X, (const float4*)Wqkv);

    dim3 ggrid(N_GEMM / 128, M_GEMM / 128);   // (24, 32)
    qkv_gemm_tc<<<ggrid, 256, 2 * STG_G>>>(bqkv, Kout, Vout);

    dim3 agrid(SEQ / 64, BS * NH);            // (32, 32)
    attn_tc<<<agrid, 128, STG_A>>>(out);
}

// round 11
// speedup vs baseline: 1.0042x; 1.0042x over previous
#include <cuda_runtime.h>
#include <cuda_fp16.h>
#include <math.h>

#define BS   2
#define SEQ  2048
#define DMODEL 1024
#define NH   16
#define HD   64
#define M_GEMM 4096
#define N_GEMM 3072
#define K_GEMM 1024
#define ELEMS (BS*SEQ*DMODEL)

// fp16 planes (packed pairs as unsigned). Device globals => no allocation.
__device__ unsigned g_Xh[M_GEMM*K_GEMM/2];                    // X hi only
__device__ unsigned g_Wh[N_GEMM*K_GEMM/2], g_Wl[N_GEMM*K_GEMM/2];  // W*64 hi/lo
__device__ unsigned g_Qh[ELEMS/2];                            // Q * 0.125*log2e, hi only
__device__ unsigned g_Kh[ELEMS/2], g_Kl[ELEMS/2];
__device__ unsigned g_Vh[ELEMS/2], g_Vl[ELEMS/2];

extern __shared__ __align__(16) char dynsmem[];

#define QSCALE (0.125f * 1.44269504088896f)   // fold 1/sqrt(64) and log2(e) into Q

// ---------------------------------------------------------------------------
// helpers
// ---------------------------------------------------------------------------
__device__ __forceinline__ unsigned pack_h(float a, float b) {
    __half2 t = __floats2half2_rn(a, b);
    return *reinterpret_cast<unsigned*>(&t);
}
__device__ __forceinline__ void split_pack_h(float a, float b, unsigned& h, unsigned& l) {
    __half ah = __float2half_rn(a);
    __half bh = __float2half_rn(b);
    __half2 hv; hv.x = ah; hv.y = bh;
    h = *reinterpret_cast<unsigned*>(&hv);
    l = pack_h(a - __half2float(ah), b - __half2float(bh));
}
__device__ __forceinline__ void mma16816(float* d, const unsigned* a, unsigned b0, unsigned b1) {
    asm volatile(
        "mma.sync.aligned.m16n8k16.row.col.f32.f16.f16.f32 "
        "{%0,%1,%2,%3}, {%4,%5,%6,%7}, {%8,%9}, {%0,%1,%2,%3};"
        : "+f"(d[0]), "+f"(d[1]), "+f"(d[2]), "+f"(d[3])
        : "r"(a[0]), "r"(a[1]), "r"(a[2]), "r"(a[3]), "r"(b0), "r"(b1));
}
__device__ __forceinline__ unsigned smem_u32(const void* p) {
    return (unsigned)__cvta_generic_to_shared(p);
}
__device__ __forceinline__ void ldsm_x4(unsigned& r0, unsigned& r1, unsigned& r2, unsigned& r3, unsigned addr) {
    asm volatile("ldmatrix.sync.aligned.m8n8.x4.shared.b16 {%0,%1,%2,%3}, [%4];"
                 : "=r"(r0), "=r"(r1), "=r"(r2), "=r"(r3) : "r"(addr));
}
__device__ __forceinline__ void ldsm_x4_t(unsigned& r0, unsigned& r1, unsigned& r2, unsigned& r3, unsigned addr) {
    asm volatile("ldmatrix.sync.aligned.m8n8.x4.trans.shared.b16 {%0,%1,%2,%3}, [%4];"
                 : "=r"(r0), "=r"(r1), "=r"(r2), "=r"(r3) : "r"(addr));
}
__device__ __forceinline__ void cp16(unsigned dst, const void* src) {
    asm volatile("cp.async.cg.shared.global [%0], [%1], 16;" :: "r"(dst), "l"(src));
}
__device__ __forceinline__ void cp_commit() { asm volatile("cp.async.commit_group;" ::: "memory"); }
__device__ __forceinline__ void cp_wait0() { asm volatile("cp.async.wait_group 0;" ::: "memory"); }
__device__ __forceinline__ void cp_wait1() { asm volatile("cp.async.wait_group 1;" ::: "memory"); }
__device__ __forceinline__ float ex2f(float x) {
    float r; asm("ex2.approx.f32 %0, %1;" : "=f"(r) : "f"(x)); return r;
}

// ---------------------------------------------------------------------------
// Kernel 0: X -> fp16 hi plane; W*64 -> fp16 hi/lo planes
// ---------------------------------------------------------------------------
__global__ void convert_planes(const float4* __restrict__ X4, const float4* __restrict__ W4)
{
    const int i0 = blockIdx.x * blockDim.x + threadIdx.x;
    const int stride = gridDim.x * blockDim.x;
    for (int idx = i0; idx < M_GEMM * K_GEMM / 4; idx += stride) {
        float4 v = X4[idx];
        g_Xh[2*idx]   = pack_h(v.x, v.y);
        g_Xh[2*idx+1] = pack_h(v.z, v.w);
    }
    for (int idx = i0; idx < N_GEMM * K_GEMM / 4; idx += stride) {
        float4 v = W4[idx];
        unsigned h0, l0, h1, l1;
        split_pack_h(v.x * 64.f, v.y * 64.f, h0, l0);
        split_pack_h(v.z * 64.f, v.w * 64.f, h1, l1);
        g_Wh[2*idx] = h0; g_Wh[2*idx+1] = h1;
        g_Wl[2*idx] = l0; g_Wl[2*idx+1] = l1;
    }
}

// ---------------------------------------------------------------------------
// Kernel 1: QKV GEMM, fp16 2-term (Xh*Wh + Xh*Wl), 2-stage cp.async pipeline.
// 128x128 tile, BK=32, 256 threads = 8 warps (2m x 4n).
// ---------------------------------------------------------------------------
#define GST 40                         // smem row stride (80B)
#define PS_G (128*GST*2)               // plane bytes 10240
#define STG_G (3*PS_G)                 // stage bytes 30720 (Ah, Bh, Bl)

__global__ __launch_bounds__(256, 2)
void qkv_gemm_tc(const float* __restrict__ bias,
                 float* __restrict__ Kout, float* __restrict__ Vout)
{
    const int tid = threadIdx.x;
    const int w = tid >> 5, lane = tid & 31;
    const int wm = w & 1, wn = w >> 1;
    const int gr = lane >> 2, qc = lane & 3;
    const int bm = blockIdx.y * 128, bn = blockIdx.x * 128;

    const unsigned sbase = smem_u32(dynsmem);
    const int lrow = tid >> 1;
    const int ch0  = (tid & 1) * 2;

    const size_t arow0 = (size_t)(bm + lrow) * (K_GEMM/2);
    const size_t brow0 = (size_t)(bn + lrow) * (K_GEMM/2);
    const unsigned doff_base = lrow * (GST*2);

    auto issue_load = [&](int kb, int s) {
        const unsigned st = sbase + s * STG_G;
        const size_t ar = arow0 + kb * 16;
        const size_t br = brow0 + kb * 16;
        #pragma unroll
        for (int c = 0; c < 2; c++) {
            const int ch = ch0 + c;
            const unsigned doff = doff_base + ch * 16;
            cp16(st          + doff, &g_Xh[ar + ch*4]);
            cp16(st + PS_G   + doff, &g_Wh[br + ch*4]);
            cp16(st + 2*PS_G + doff, &g_Wl[br + ch*4]);
        }
    };

    float acc[4][4][4];
    #pragma unroll
    for (int i = 0; i < 4; i++)
        #pragma unroll
        for (int j = 0; j < 4; j++)
            #pragma unroll
            for (int e = 0; e < 4; e++) acc[i][j][e] = 0.f;

    issue_load(0, 0); cp_commit();

    const unsigned acol_b = (lane >> 4) * 16;
    const unsigned arow_f = (lane & 15);
    const unsigned bcol_b = ((lane >> 3) & 1) * 16;
    const unsigned brow_f = ((lane >> 4) << 3) + (lane & 7);

    #pragma unroll 1
    for (int kb = 0; kb < 32; kb++) {
        const int cur = kb & 1;
        if (kb < 31) { issue_load(kb + 1, cur ^ 1); cp_commit(); cp_wait1(); }
        else cp_wait0();
        __syncthreads();

        const unsigned sAh = sbase + cur * STG_G;
        const unsigned sBh = sAh + PS_G;
        const unsigned sBl = sAh + 2*PS_G;

        #pragma unroll
        for (int kt = 0; kt < 2; kt++) {
            unsigned ah[4][4];
            const unsigned acol = kt*32 + acol_b;
            #pragma unroll
            for (int i = 0; i < 4; i++) {
                const unsigned aoff = (unsigned)(wm*64 + i*16 + arow_f) * (GST*2) + acol;
                ldsm_x4(ah[i][0], ah[i][1], ah[i][2], ah[i][3], sAh + aoff);
            }
            const unsigned bcol = kt*32 + bcol_b;
            #pragma unroll
            for (int jp = 0; jp < 2; jp++) {
                const unsigned boff = (unsigned)(wn*32 + jp*16 + brow_f) * (GST*2) + bcol;
                unsigned h0,h1,h2,h3, l0,l1,l2,l3;
                ldsm_x4(h0, h1, h2, h3, sBh + boff);
                ldsm_x4(l0, l1, l2, l3, sBl + boff);
                #pragma unroll
                for (int i = 0; i < 4; i++) {
                    mma16816(acc[i][2*jp],   ah[i], h0, h1);
                    mma16816(acc[i][2*jp],   ah[i], l0, l1);
                    mma16816(acc[i][2*jp+1], ah[i], h2, h3);
                    mma16816(acc[i][2*jp+1], ah[i], l2, l3);
                }
            }
        }
        __syncthreads();
    }

    // ---- epilogue: acc/64 + bias; scatter fp32 K/V + fp16 planes ----
    #pragma unroll
    for (int i = 0; i < 4; i++) {
        #pragma unroll
        for (int eh = 0; eh < 2; eh++) {
            const int m = bm + wm*64 + i*16 + gr + eh*8;
            const int bb = m >> 11;
            const int s  = m & (SEQ - 1);
            #pragma unroll
            for (int j = 0; j < 4; j++) {
                const int n = bn + wn*32 + j*8 + qc*2;     // even
                const int t = n >> 10;
                const int hh = (n >> 6) & (NH - 1);
                const int d = n & (HD - 1);
                const float2 bv = *(const float2*)&bias[n];
                const float v0 = acc[i][j][2*eh]   * 0.015625f + bv.x;
                const float v1 = acc[i][j][2*eh+1] * 0.015625f + bv.y;
                const size_t idx = (((size_t)(bb*NH + hh))*SEQ + s)*HD + d;
                if (t == 0) {
                    g_Qh[idx>>1] = pack_h(v0 * QSCALE, v1 * QSCALE);
                } else if (t == 1) {
                    unsigned hp, lp; split_pack_h(v0, v1, hp, lp);
                    *(float2*)&Kout[idx] = make_float2(v0, v1);
                    g_Kh[idx>>1] = hp; g_Kl[idx>>1] = lp;
                } else {
                    unsigned hp, lp; split_pack_h(v0, v1, hp, lp);
                    *(float2*)&Vout[idx] = make_float2(v0, v1);
                    g_Vh[idx>>1] = hp; g_Vl[idx>>1] = lp;
                }
            }
        }
    }
}

// ---------------------------------------------------------------------------
// Kernel 2: causal flash attention, fp16. S = Qh*(Kh+Kl) (2 MMAs/step),
// PV 3-term. Single-buffered smem, 4 blocks/SM, exp2-domain softmax.
// ---------------------------------------------------------------------------
#define KST 72
#define PS_A (64*KST*2)                // 9216
#define STG_A (4*PS_A)                 // 36864

__global__ __launch_bounds__(128, 4)
void attn_tc(float* __restrict__ Out)
{
    const int bh = blockIdx.y;
    const int b = bh >> 4, h = bh & (NH - 1);
    const int qt = gridDim.x - 1 - blockIdx.x;     // heavy blocks first
    const int tid = threadIdx.x, w = tid >> 5, lane = tid & 31;
    const int gr = lane >> 2, qc = lane & 3;
    const int m0 = qt * 64 + w * 16;

    const unsigned sbase = smem_u32(dynsmem);
    const size_t qbase = (size_t)bh * SEQ;

    // Q hi fragments only (pre-scaled by 0.125*log2e)
    unsigned qh[4][4];
    #pragma unroll
    for (int kk = 0; kk < 4; kk++) {
        #pragma unroll
        for (int e = 0; e < 4; e++) {
            const int r = m0 + gr + (e & 1) * 8;
            const int c = kk*16 + qc*2 + (e >> 1) * 8;
            qh[kk][e] = g_Qh[(qbase + r) * 32 + (c >> 1)];
        }
    }

    float Oa[8][4];
    #pragma unroll
    for (int jd = 0; jd < 8; jd++)
        #pragma unroll
        for (int e = 0; e < 4; e++) Oa[jd][e] = 0.f;
    float mrow0 = -INFINITY, mrow1 = -INFINITY, lsum0 = 0.f, lsum1 = 0.f;

    const int lrow = tid >> 1;
    const int ch0  = (tid & 1) * 4;
    const unsigned doff_base = lrow * (KST*2);

    const unsigned sKh = sbase;
    const unsigned sKl = sbase + PS_A;
    const unsigned sVh = sbase + 2*PS_A;
    const unsigned sVl = sbase + 3*PS_A;

    const unsigned krow_f = ((lane >> 4) << 3) + (lane & 7);
    const unsigned kcol_b = ((lane >> 3) & 1) * 16;
    const unsigned vrow_f = (lane & 15);
    const unsigned vcol_b = (lane >> 4) * 16;

    #pragma unroll 1
    for (int kt = 0; kt <= qt; kt++) {
        // ---- single-buffer load (cross-block overlap hides latency) ----
        const size_t rowb = (qbase + kt*64 + lrow) * 32;
        #pragma unroll
        for (int c = 0; c < 4; c++) {
            const int ch = ch0 + c;
            const unsigned doff = doff_base + ch * 16;
            cp16(sKh + doff, &g_Kh[rowb + ch*4]);
            cp16(sKl + doff, &g_Kl[rowb + ch*4]);
            cp16(sVh + doff, &g_Vh[rowb + ch*4]);
            cp16(sVl + doff, &g_Vl[rowb + ch*4]);
        }
        cp_commit(); cp_wait0();
        __syncthreads();

        // ---- S = Qh (Kh + Kl): 2 MMAs per fragment pair ----
        float S[8][4];
        #pragma unroll
        for (int j = 0; j < 8; j++)
            #pragma unroll
            for (int e = 0; e < 4; e++) S[j][e] = 0.f;

        #pragma unroll
        for (int kk = 0; kk < 4; kk++) {
            const unsigned kcol = kk*32 + kcol_b;
            #pragma unroll
            for (int jp = 0; jp < 4; jp++) {
                const unsigned koff = (jp*16 + krow_f) * (KST*2) + kcol;
                unsigned h0,h1,h2,h3, l0,l1,l2,l3;
                ldsm_x4(h0, h1, h2, h3, sKh + koff);
                ldsm_x4(l0, l1, l2, l3, sKl + koff);
                mma16816(S[2*jp],   qh[kk], h0, h1);
                mma16816(S[2*jp],   qh[kk], l0, l1);
                mma16816(S[2*jp+1], qh[kk], h2, h3);
                mma16816(S[2*jp+1], qh[kk], l2, l3);
            }
        }

        // ---- causal mask on diagonal tile ----
        if (kt == qt) {
            const int r0 = w*16 + gr, r1 = r0 + 8;
            #pragma unroll
            for (int j = 0; j < 8; j++) {
                const int cn = j*8 + qc*2;
                if (cn     > r0) S[j][0] = -1e30f;
                if (cn + 1 > r0) S[j][1] = -1e30f;
                if (cn     > r1) S[j][2] = -1e30f;
                if (cn + 1 > r1) S[j][3] = -1e30f;
            }
        }

        // ---- online softmax (base-2 domain) ----
        float mx0 = -1e30f, mx1 = -1e30f;
        #pragma unroll
        for (int j = 0; j < 8; j++) {
            mx0 = fmaxf(mx0, fmaxf(S[j][0], S[j][1]));
            mx1 = fmaxf(mx1, fmaxf(S[j][2], S[j][3]));
        }
        mx0 = fmaxf(mx0, __shfl_xor_sync(0xffffffff, mx0, 1));
        mx0 = fmaxf(mx0, __shfl_xor_sync(0xffffffff, mx0, 2));
        mx1 = fmaxf(mx1, __shfl_xor_sync(0xffffffff, mx1, 1));
        mx1 = fmaxf(mx1, __shfl_xor_sync(0xffffffff, mx1, 2));

        const float mnew0 = fmaxf(mrow0, mx0), mnew1 = fmaxf(mrow1, mx1);
        const float alpha0 = ex2f(mrow0 - mnew0), alpha1 = ex2f(mrow1 - mnew1);
        mrow0 = mnew0; mrow1 = mnew1;
        lsum0 *= alpha0; lsum1 *= alpha1;
        #pragma unroll
        for (int jd = 0; jd < 8; jd++) {
            Oa[jd][0] *= alpha0; Oa[jd][1] *= alpha0;
            Oa[jd][2] *= alpha1; Oa[jd][3] *= alpha1;
        }

        float rs0 = 0.f, rs1 = 0.f;
        #pragma unroll
        for (int j = 0; j < 8; j++) {
            S[j][0] = ex2f(S[j][0] - mnew0);
            S[j][1] = ex2f(S[j][1] - mnew0);
            S[j][2] = ex2f(S[j][2] - mnew1);
            S[j][3] = ex2f(S[j][3] - mnew1);
            rs0 += S[j][0] + S[j][1];
            rs1 += S[j][2] + S[j][3];
        }
        rs0 += __shfl_xor_sync(0xffffffff, rs0, 1);
        rs0 += __shfl_xor_sync(0xffffffff, rs0, 2);
        rs1 += __shfl_xor_sync(0xffffffff, rs1, 1);
        rs1 += __shfl_xor_sync(0xffffffff, rs1, 2);
        lsum0 += rs0; lsum1 += rs1;

        // ---- O += P V (3-term fp16) ----
        #pragma unroll
        for (int kk = 0; kk < 4; kk++) {
            unsigned pp[4], pl[4];
            const int j0 = kk*2, j1 = kk*2 + 1;
            split_pack_h(S[j0][0], S[j0][1], pp[0], pl[0]);
            split_pack_h(S[j0][2], S[j0][3], pp[1], pl[1]);
            split_pack_h(S[j1][0], S[j1][1], pp[2], pl[2]);
            split_pack_h(S[j1][2], S[j1][3], pp[3], pl[3]);
            const unsigned vrow = (kk*16 + vrow_f) * (KST*2);
            #pragma unroll
            for (int jp = 0; jp < 4; jp++) {
                const unsigned voff = vrow + jp*32 + vcol_b;
                unsigned vh0,vh1,vh2,vh3, vl0,vl1,vl2,vl3;
                ldsm_x4_t(vh0, vh1, vh2, vh3, sVh + voff);
                ldsm_x4_t(vl0, vl1, vl2, vl3, sVl + voff);
                mma16816(Oa[2*jp],   pp, vh0, vh1);
                mma16816(Oa[2*jp],   pp, vl0, vl1);
                mma16816(Oa[2*jp],   pl, vh0, vh1);
                mma16816(Oa[2*jp+1], pp, vh2, vh3);
                mma16816(Oa[2*jp+1], pp, vl2, vl3);
                mma16816(Oa[2*jp+1], pl, vh2, vh3);
            }
        }
        __syncthreads();
    }

    const float inv0 = 1.f / lsum0, inv1 = 1.f / lsum1;
    float* Op = Out + ((size_t)b * SEQ + m0) * DMODEL + h * HD;
    #pragma unroll
    for (int jd = 0; jd < 8; jd++) {
        const int c = jd*8 + qc*2;
        float2 v0; v0.x = Oa[jd][0] * inv0; v0.y = Oa[jd][1] * inv0;
        float2 v1; v1.x = Oa[jd][2] * inv1; v1.y = Oa[jd][3] * inv1;
        *(float2*)&Op[(size_t)gr * DMODEL + c]       = v0;
        *(float2*)&Op[(size_t)(gr + 8) * DMODEL + c] = v1;
    }
}

// ---------------------------------------------------------------------------
extern "C" void kernel_launch(void* const* d_in, const int* in_sizes, int n_in,
                              void* d_out, int out_size)
{
    const float* X    = (const float*)d_in[0];
    const float* Wqkv = (const float*)d_in[1];
    const float* bqkv = (const float*)d_in[2];

    float* out  = (float*)d_out;
    float* Kout = (float*)d_out + ELEMS;
    float* Vout = (float*)d_out + 2 * (size_t)ELEMS;

    static bool attr_done = false;
    if (!attr_done) {
        cudaFuncSetAttribute(qkv_gemm_tc, cudaFuncAttributeMaxDynamicSharedMemorySize, 2 * STG_G);
        cudaFuncSetAttribute(attn_tc,     cudaFuncAttributeMaxDynamicSharedMemorySize, STG_A);
        attr_done = true;
    }

    convert_planes<<<512, 256>>>((const float4*)X, (const float4*)Wqkv);

    dim3 ggrid(N_GEMM / 128, M_GEMM / 128);   // (24, 32)
    qkv_gemm_tc<<<ggrid, 256, 2 * STG_G>>>(bqkv, Kout, Vout);

    dim3 agrid(SEQ / 64, BS * NH);            // (32, 32)
    attn_tc<<<agrid, 128, STG_A>>>(out);
}